// round 3
// baseline (speedup 1.0000x reference)
#include <cuda_runtime.h>
#include <math.h>

#define BB 256
#define TT 512
#define KK 128

// Scratch (allocation-free rule: __device__ globals).
__device__ unsigned char g_bp[(size_t)BB * TT * KK];   // backpointers, 16.8 MB
__device__ float g_nll[BB];
__device__ unsigned int g_done = 0;

// smem layout (bytes):
//   [0, 65536)        s_mat : Viterbi trans (row-major), reused as bp cache. LSE: final-sum scratch.
//   [65536, 67584)    s_p   : LSE double-buffered duplicated p vector, 2 x 256 floats
//   [67584, 67600)    s_M   : 2 floats (double-buffered running M)
//   [67600, 68624)    s_cand: 8 warps x 16 uint2 candidates
//   [68624, 68656)    s_wmax: 8 floats
//   [68656, 68688)    s_wcnt: 8 ints
//   [68688, 68816)    s_red : 16 floats + 16 ints
//   [68816, 69840)    s_ord : 256 ints (descending-length order)
#define OFF_P    65536
#define OFF_M    67584
#define OFF_CAND 67600
#define OFF_WMAX 68624
#define OFF_WCNT 68656
#define OFF_RED  68688
#define OFF_ORD  68816
#define SMEM_BYTES 69840

#define FMA2(acc, a, b) asm("fma.rn.f32x2 %0, %1, %2, %0;" : "+l"(acc) : "l"(a), "l"(b))
#define ADD2(d, a, b)   asm("add.rn.f32x2 %0, %1, %2;" : "=l"(d) : "l"(a), "l"(b))

extern "C" __global__ void __launch_bounds__(256, 2) crf_fused(
    const float* __restrict__ logits,
    const int*   __restrict__ labels,
    const int*   __restrict__ seq_lens,
    const float* __restrict__ trans,
    float* __restrict__ out)
{
    extern __shared__ char smem_raw[];
    float* s_mat  = (float*)smem_raw;
    float* s_p    = (float*)(smem_raw + OFF_P);
    float* s_M    = (float*)(smem_raw + OFF_M);
    uint2* s_cand = (uint2*)(smem_raw + OFF_CAND);
    float* s_wmax = (float*)(smem_raw + OFF_WMAX);
    int*   s_wcnt = (int*)  (smem_raw + OFF_WCNT);
    float* s_red  = (float*)(smem_raw + OFF_RED);
    int*   s_redi = (int*)  (s_red + 16);
    int*   s_ord  = (int*)  (smem_raw + OFF_ORD);

    const int tid  = threadIdx.x;
    const int lane = tid & 31;
    const int wid  = tid >> 5;

    // ----- prologue: rank batches by descending length (tid ranks batch tid) -----
    {
        int my = __ldg(&seq_lens[tid]);
        int r = 0;
        #pragma unroll 8
        for (int jb = 0; jb < BB; ++jb) {
            int lj = __ldg(&seq_lens[jb]);
            r += (lj > my) || (lj == my && jb < tid);
        }
        s_ord[r] = tid;
    }
    __syncthreads();

    const bool is_vit = (blockIdx.x & 1) == 0;   // interleave kinds, longest first
    const int b   = s_ord[blockIdx.x >> 1];
    const int len = seq_lens[b];
    const float* lgb = logits + (size_t)b * TT * KK;

    if (is_vit) {
        // ================= Viterbi (exact candidate pruning, 2-way scan split) =================
        const int j = tid >> 1;       // state 0..127
        const int v = tid & 1;        // candidate-scan half
        for (int idx = tid; idx < KK * KK; idx += 256) s_mat[idx] = trans[idx];
        float alpha = lgb[j];
        __syncthreads();

        unsigned char* bp_out = &g_bp[(size_t)b * TT * KK];
        for (int t = 1; t < len; ++t) {
            float emit = __ldg(&lgb[t * KK + j]);
            float wm = alpha;
            #pragma unroll
            for (int m = 16; m > 0; m >>= 1) wm = fmaxf(wm, __shfl_xor_sync(0xFFFFFFFFu, wm, m));
            if (lane == 0) s_wmax[wid] = wm;
            __syncthreads();
            float amax = s_wmax[0];
            #pragma unroll
            for (int w = 1; w < 8; ++w) amax = fmaxf(amax, s_wmax[w]);
            // trans in [0,1): alpha <= amax-1 is dominated; margin covers fp rounding.
            bool keep = (v == 0) && (alpha >= amax - 1.002f);
            unsigned mask = __ballot_sync(0xFFFFFFFFu, keep);
            if (keep) {
                int pos = __popc(mask & ((1u << lane) - 1u));
                s_cand[wid * 16 + pos] = make_uint2(__float_as_uint(alpha), (unsigned)j);
            }
            if (lane == 0) s_wcnt[wid] = __popc(mask);
            __syncthreads();
            float best = -INFINITY; int bi = KK;
            #pragma unroll 1
            for (int w = 0; w < 8; ++w) {
                int cnt = s_wcnt[w];
                const uint2* lst = &s_cand[w * 16];
                for (int c = v; c < cnt; c += 2) {   // ascending i within subset
                    uint2 e = lst[c];
                    float s = __uint_as_float(e.x) + s_mat[e.y * KK + j];
                    if (s > best) { best = s; bi = (int)e.y; }
                }
            }
            {   // combine subsets; smaller index wins ties -> global first-argmax
                float ob = __shfl_xor_sync(0xFFFFFFFFu, best, 1);
                int   oi = __shfl_xor_sync(0xFFFFFFFFu, bi, 1);
                if (ob > best || (ob == best && oi < bi)) { best = ob; bi = oi; }
            }
            alpha = best + emit;
            if (v == 0) bp_out[t * KK + j] = (unsigned char)bi;
        }
        // final argmax (dup lanes harmless; first-index tie break)
        {
            float bv = alpha; int bidx = j;
            #pragma unroll
            for (int m = 16; m > 0; m >>= 1) {
                float ov = __shfl_xor_sync(0xFFFFFFFFu, bv, m);
                int   oi = __shfl_xor_sync(0xFFFFFFFFu, bidx, m);
                if (ov > bv || (ov == bv && oi < bidx)) { bv = ov; bidx = oi; }
            }
            if (lane == 0) { s_red[wid] = bv; s_redi[wid] = bidx; }
        }
        __syncthreads();
        if (tid == 0) {
            float bv = s_red[0]; int bidx = s_redi[0];
            #pragma unroll
            for (int w = 1; w < 8; ++w) {
                float wv = s_red[w]; int wi = s_redi[w];
                if (wv > bv || (wv == bv && wi < bidx)) { bv = wv; bidx = wi; }
            }
            s_redi[8] = bidx;
        }
        __syncthreads();
        const int last = s_redi[8];
        // reuse s_mat as bp cache for the serial chase
        unsigned char* s_bp = (unsigned char*)s_mat;
        {
            const int nbytes = (len - 1) * KK;   // multiple of 16, <= 65408
            const int4* src = (const int4*)&g_bp[((size_t)b * TT + 1) * KK];
            int4* dst = (int4*)s_bp;
            for (int i = tid; i * 16 < nbytes; i += 256) dst[i] = src[i];
        }
        __syncthreads();
        if (tid == 0) {
            float* pred = out + 1 + (size_t)b * TT;
            int tag = last;
            for (int t = TT - 1; t >= len - 1; --t) pred[t] = (float)tag;
            for (int t = len - 1; t >= 1; --t) {
                tag = s_bp[(t - 1) * KK + tag];
                pred[t - 1] = (float)tag;
            }
        }
    } else {
        // ================= CRF log-norm: register matrix + FFMA2, no max-reduce =================
        const int jp = tid >> 2;      // column pair 0..63
        const int h  = tid & 3;       // i-quarter
        const int i0 = h * 32;

        unsigned long long m[32];     // (E[i][2jp], E[i][2jp+1]) packed
        #pragma unroll
        for (int q = 0; q < 32; ++q) {
            float2 tv = *(const float2*)&trans[(i0 + q) * KK + 2 * jp];
            unsigned e0 = __float_as_uint(__expf(tv.x));
            unsigned e1 = __float_as_uint(__expf(tv.y));
            asm("mov.b64 %0, {%1, %2};" : "=l"(m[q]) : "r"(e0), "r"(e1));
        }
        float2 a0v = *(const float2*)&lgb[2 * jp];
        float aX = a0v.x, aY = a0v.y;
        float M = __ldg(&lgb[0]);     // alpha_0[0]
        int cur = 0;

        for (int t = 1; t < len; ++t) {
            float2 emit = *(const float2*)&lgb[t * KK + 2 * jp];
            if (h == 0) {
                float p0 = __expf(aX - M), p1 = __expf(aY - M);
                *(float4*)&s_p[cur * 256 + 4 * jp] = make_float4(p0, p0, p1, p1);
                if (jp == 0) s_M[cur] = aX;
            }
            __syncthreads();
            float Mr = s_M[cur];
            const ulonglong2* pv = (const ulonglong2*)&s_p[cur * 256 + 2 * i0];
            unsigned long long acc0 = 0ull, acc1 = 0ull, acc2 = 0ull, acc3 = 0ull;
            #pragma unroll
            for (int qq = 0; qq < 16; qq += 2) {
                ulonglong2 pA = pv[qq];
                FMA2(acc0, pA.x, m[2 * qq]);
                FMA2(acc1, pA.y, m[2 * qq + 1]);
                ulonglong2 pB = pv[qq + 1];
                FMA2(acc2, pB.x, m[2 * qq + 2]);
                FMA2(acc3, pB.y, m[2 * qq + 3]);
            }
            unsigned long long s01, s23, stot;
            ADD2(s01, acc0, acc1);
            ADD2(s23, acc2, acc3);
            ADD2(stot, s01, s23);
            unsigned lo, hi;
            asm("mov.b64 {%0, %1}, %2;" : "=r"(lo), "=r"(hi) : "l"(stot));
            float dx = __uint_as_float(lo), dy = __uint_as_float(hi);
            // butterfly over the 4 i-quarters (lanes bits 0,1); commutative-add => identical
            dx += __shfl_xor_sync(0xFFFFFFFFu, dx, 1);
            dx += __shfl_xor_sync(0xFFFFFFFFu, dx, 2);
            dy += __shfl_xor_sync(0xFFFFFFFFu, dy, 1);
            dy += __shfl_xor_sync(0xFFFFFFFFu, dy, 2);
            aX = __logf(dx) + M + emit.x;
            aY = __logf(dy) + M + emit.y;
            M = Mr;          // = alpha_{t-1}[0], 1-step stale for next exp
            cur ^= 1;
        }

        // logZ = logsumexp(alpha), deterministic fixed-order reduction
        float v = fmaxf(aX, aY);
        #pragma unroll
        for (int mm = 16; mm > 0; mm >>= 1) v = fmaxf(v, __shfl_xor_sync(0xFFFFFFFFu, v, mm));
        if (lane == 0) s_wmax[wid] = v;
        __syncthreads();
        float Mx = s_wmax[0];
        #pragma unroll
        for (int w = 1; w < 8; ++w) Mx = fmaxf(Mx, s_wmax[w]);
        float e = (h == 0) ? (__expf(aX - Mx) + __expf(aY - Mx)) : 0.f;
        #pragma unroll
        for (int mm = 16; mm > 0; mm >>= 1) e += __shfl_xor_sync(0xFFFFFFFFu, e, mm);
        if (lane == 0) s_red[wid] = e;

        // sequence score
        const int* lab = labels + b * TT;
        float sc = 0.f;
        for (int t = tid; t < len; t += 256) {
            int l = lab[t];
            sc += lgb[t * KK + l];
            if (t >= 1) sc += trans[lab[t - 1] * KK + l];
        }
        #pragma unroll
        for (int mm = 16; mm > 0; mm >>= 1) sc += __shfl_xor_sync(0xFFFFFFFFu, sc, mm);
        if (lane == 0) s_red[8 + wid] = sc;
        __syncthreads();

        if (tid == 0) {
            float S = 0.f, SC = 0.f;
            #pragma unroll
            for (int w = 0; w < 8; ++w) { S += s_red[w]; SC += s_red[8 + w]; }
            g_nll[b] = (__logf(S) + Mx) - SC;
            __threadfence();
            unsigned dv = atomicAdd(&g_done, 1u);
            s_redi[0] = ((dv & 255u) == 255u) ? 1 : 0;
        }
        __syncthreads();
        if (s_redi[0]) {
            // last LSE CTA: deterministic tree sum of all nll -> loss
            __threadfence();
            float* sb = (float*)smem_raw;   // s_mat region unused by LSE
            sb[tid] = g_nll[tid];
            __syncthreads();
            for (int mm = 128; mm > 0; mm >>= 1) {
                if (tid < mm) sb[tid] += sb[tid + mm];
                __syncthreads();
            }
            if (tid == 0) out[0] = sb[0];
        }
    }
}

extern "C" void kernel_launch(void* const* d_in, const int* in_sizes, int n_in,
                              void* d_out, int out_size)
{
    const float* logits   = (const float*)d_in[0];
    const int*   labels   = (const int*)d_in[1];
    const int*   seq_lens = (const int*)d_in[2];
    const float* trans    = (const float*)d_in[3];
    float* out = (float*)d_out;

    cudaFuncSetAttribute(crf_fused, cudaFuncAttributeMaxDynamicSharedMemorySize, SMEM_BYTES);
    crf_fused<<<2 * BB, 256, SMEM_BYTES>>>(logits, labels, seq_lens, trans, out);
}

// round 4
// speedup vs baseline: 2.1319x; 2.1319x over previous
#include <cuda_runtime.h>
#include <math.h>

#define BB 256
#define TT 512
#define KK 128

// Scratch (allocation-free rule: __device__ globals).
__device__ unsigned char g_bp[(size_t)BB * TT * KK];   // backpointers, 16.8 MB
__device__ float g_nll[BB];

// smem layout (bytes):
//   [0, 67584)        s_mat : Viterbi = trans row-major (64KB, reused as bp cache)
//                             LSE     = exp(trans) transposed, rows padded to 132 floats
//   [67584, 71680)    s_p   : LSE p vectors, [2 buf][2 batch][128] floats
//   [71680, 71696)    s_M   : 4 floats ([buf][batch] stale M)
//   [71696, 72720)    s_cand: 4 warps x 32 uint2 candidates (also prologue len cache)
//   [72720, 72736)    s_wkey: 4 u32 per-warp max keys
//   [72736, 72752)    s_wcnt: 4 ints
//   [72752, 72880)    s_red : 16 floats + 16 ints
//   [72880, 73904)    s_ord : 256 ints (descending-length order)
#define OFF_P    67584
#define OFF_M    71680
#define OFF_CAND 71696
#define OFF_WKEY 72720
#define OFF_WCNT 72736
#define OFF_RED  72752
#define OFF_ORD  72880
#define SMEM_BYTES 73904

#define FMA2(acc, a, b) asm("fma.rn.f32x2 %0, %1, %2, %0;" : "+l"(acc) : "l"(a), "l"(b))
#define ADD2(d, a, b)   asm("add.rn.f32x2 %0, %1, %2;" : "=l"(d) : "l"(a), "l"(b))

// order-preserving float<->uint key (no NaNs in this data)
__device__ __forceinline__ unsigned fkey(float f) {
    unsigned u = __float_as_uint(f);
    return (u & 0x80000000u) ? ~u : (u | 0x80000000u);
}
__device__ __forceinline__ float fval(unsigned k) {
    return __uint_as_float((k & 0x80000000u) ? (k & 0x7FFFFFFFu) : ~k);
}

extern "C" __global__ void __launch_bounds__(128, 3) crf_fwd(
    const float* __restrict__ logits,
    const int*   __restrict__ labels,
    const int*   __restrict__ seq_lens,
    const float* __restrict__ trans,
    float* __restrict__ out)
{
    extern __shared__ char smem_raw[];
    float*    s_mat  = (float*)smem_raw;
    float*    s_p    = (float*)(smem_raw + OFF_P);
    float*    s_M    = (float*)(smem_raw + OFF_M);
    uint2*    s_cand = (uint2*)(smem_raw + OFF_CAND);
    unsigned* s_wkey = (unsigned*)(smem_raw + OFF_WKEY);
    int*      s_wcnt = (int*)(smem_raw + OFF_WCNT);
    float*    s_red  = (float*)(smem_raw + OFF_RED);
    int*      s_redi = (int*)(s_red + 16);
    int*      s_ord  = (int*)(smem_raw + OFF_ORD);

    const int tid  = threadIdx.x;
    const int lane = tid & 31;
    const int wid  = tid >> 5;

    // ----- prologue: rank batches by descending length (from smem) -----
    {
        int* s_len = (int*)(smem_raw + OFF_CAND);     // reuse cand region
        for (int bt = tid; bt < BB; bt += 128) s_len[bt] = __ldg(&seq_lens[bt]);
        __syncthreads();
        for (int bt = tid; bt < BB; bt += 128) {
            int my = s_len[bt];
            int r = 0;
            #pragma unroll 8
            for (int jb = 0; jb < BB; ++jb) {
                int lj = s_len[jb];
                r += (lj > my) || (lj == my && jb < bt);
            }
            s_ord[r] = bt;
        }
        __syncthreads();
    }

    // grid 384: group g -> 2 Viterbi CTAs (ranks 2g, 2g+1) + 1 LSE CTA (pair 2g,2g+1)
    const int g = blockIdx.x / 3;
    const int r = blockIdx.x - 3 * g;
    const bool is_vit = (r < 2);

    if (is_vit) {
        // ================= Viterbi: exact candidate pruning =================
        const int b   = s_ord[2 * g + r];
        const int len = seq_lens[b];
        const float* lgb = logits + (size_t)b * TT * KK;

        for (int idx = tid; idx < KK * KK; idx += 128) s_mat[idx] = trans[idx];
        float alpha = lgb[tid];
        __syncthreads();

        unsigned char* bp_out = &g_bp[(size_t)b * TT * KK];
        float e_cur = (len > 1) ? __ldg(&lgb[KK + tid]) : 0.f;
        for (int t = 1; t < len; ++t) {
            int tn = (t + 1 < len) ? t + 1 : t;
            float e_next = __ldg(&lgb[tn * KK + tid]);      // prefetch next emission
            unsigned wk = __reduce_max_sync(0xFFFFFFFFu, fkey(alpha));
            if (lane == 0) s_wkey[wid] = wk;
            __syncthreads();
            unsigned ak = max(max(s_wkey[0], s_wkey[1]), max(s_wkey[2], s_wkey[3]));
            float amax = fval(ak);
            // trans in [0,1): alpha <= amax-1 dominated; margin >> ulp(|alpha|).
            bool keep = alpha >= amax - 1.002f;
            unsigned mask = __ballot_sync(0xFFFFFFFFu, keep);
            if (keep) {
                int pos = __popc(mask & ((1u << lane) - 1u));
                s_cand[wid * 32 + pos] = make_uint2(__float_as_uint(alpha), (unsigned)tid);
            }
            if (lane == 0) s_wcnt[wid] = __popc(mask);
            __syncthreads();
            float best = -INFINITY; int bi = 0;
            #pragma unroll 1
            for (int w = 0; w < 4; ++w) {
                int cnt = s_wcnt[w];
                const uint2* lst = &s_cand[w * 32];
                for (int c = 0; c < cnt; ++c) {      // ascending i: strict > keeps first argmax
                    uint2 e = lst[c];
                    float s = __uint_as_float(e.x) + s_mat[e.y * KK + tid];
                    if (s > best) { best = s; bi = (int)e.y; }
                }
            }
            alpha = best + e_cur;
            e_cur = e_next;
            bp_out[t * KK + tid] = (unsigned char)bi;
        }
        // final argmax, first-index tie break
        {
            float bv = alpha; int bidx = tid;
            #pragma unroll
            for (int m = 16; m > 0; m >>= 1) {
                float ov = __shfl_xor_sync(0xFFFFFFFFu, bv, m);
                int   oi = __shfl_xor_sync(0xFFFFFFFFu, bidx, m);
                if (ov > bv || (ov == bv && oi < bidx)) { bv = ov; bidx = oi; }
            }
            if (lane == 0) { s_red[wid] = bv; s_redi[wid] = bidx; }
        }
        __syncthreads();
        int last;
        {
            float bv = s_red[0]; int bidx = s_redi[0];
            #pragma unroll
            for (int w = 1; w < 4; ++w) {
                float wv = s_red[w]; int wi = s_redi[w];
                if (wv > bv || (wv == bv && wi < bidx)) { bv = wv; bidx = wi; }
            }
            last = bidx;
        }
        __syncthreads();   // done with s_mat -> reuse as bp cache

        unsigned char* s_bp = (unsigned char*)s_mat;
        {
            const int nbytes = (len - 1) * KK;        // multiple of 16, <= 65408
            const int4* src = (const int4*)&g_bp[((size_t)b * TT + 1) * KK];
            int4* dst = (int4*)s_bp;
            for (int i = tid; i * 16 < nbytes; i += 128) dst[i] = src[i];
        }
        __syncthreads();
        if (tid == 0) {
            float* pred = out + 1 + (size_t)b * TT;
            int tag = last;
            for (int t = TT - 1; t >= len - 1; --t) pred[t] = (float)tag;
            for (int t = len - 1; t >= 1; --t) {
                tag = s_bp[(t - 1) * KK + tag];
                pred[t - 1] = (float)tag;
            }
        }
    } else {
        // ================= LSE: 2 batches/CTA, FFMA2 matvec, stale-M =================
        const int bA = s_ord[2 * g];        // longer (sorted desc)
        const int bB = s_ord[2 * g + 1];
        const int lenA = seq_lens[bA];
        const int lenB = seq_lens[bB];
        const float* lgA = logits + (size_t)bA * TT * KK;
        const float* lgB = logits + (size_t)bB * TT * KK;

        // transposed exp(trans), padded rows (132 floats): row j holds E[0..127][j]
        for (int idx = tid; idx < KK * KK; idx += 128) {
            int i = idx >> 7, j = idx & 127;
            s_mat[j * 132 + i] = __expf(trans[idx]);
        }
        float aA = lgA[tid], aB = lgB[tid];
        float MA = __ldg(&lgA[0]), MB = __ldg(&lgB[0]);
        __syncthreads();

        const ulonglong2* mrow = (const ulonglong2*)(s_mat + tid * 132);
        int cur = 0;
        float eA = (lenA > 1) ? __ldg(&lgA[KK + tid]) : 0.f;
        float eB = (lenB > 1) ? __ldg(&lgB[KK + tid]) : 0.f;

        for (int t = 1; t < lenA; ++t) {
            int tn = (t + 1 < lenA) ? t + 1 : t;
            float nA = __ldg(&lgA[tn * KK + tid]);         // prefetch
            float nB = __ldg(&lgB[tn * KK + tid]);
            s_p[cur * 256 + tid]       = __expf(aA - MA);
            s_p[cur * 256 + 128 + tid] = __expf(aB - MB);
            if (tid == 0) { s_M[cur * 2] = aA; s_M[cur * 2 + 1] = aB; }
            __syncthreads();
            float MrA = s_M[cur * 2], MrB = s_M[cur * 2 + 1];
            const ulonglong2* pvA = (const ulonglong2*)(s_p + cur * 256);
            const ulonglong2* pvB = (const ulonglong2*)(s_p + cur * 256 + 128);
            unsigned long long a0 = 0, a1 = 0, a2 = 0, a3 = 0;
            unsigned long long c0 = 0, c1 = 0, c2 = 0, c3 = 0;
            #pragma unroll 8
            for (int q = 0; q < 32; ++q) {
                ulonglong2 mq = mrow[q];
                ulonglong2 pA = pvA[q];
                ulonglong2 pB = pvB[q];
                if (q & 1) {
                    FMA2(a2, pA.x, mq.x); FMA2(a3, pA.y, mq.y);
                    FMA2(c2, pB.x, mq.x); FMA2(c3, pB.y, mq.y);
                } else {
                    FMA2(a0, pA.x, mq.x); FMA2(a1, pA.y, mq.y);
                    FMA2(c0, pB.x, mq.x); FMA2(c1, pB.y, mq.y);
                }
            }
            unsigned long long sA, sB, t0, t1;
            ADD2(t0, a0, a1); ADD2(t1, a2, a3); ADD2(sA, t0, t1);
            ADD2(t0, c0, c1); ADD2(t1, c2, c3); ADD2(sB, t0, t1);
            unsigned lo, hi;
            asm("mov.b64 {%0, %1}, %2;" : "=r"(lo), "=r"(hi) : "l"(sA));
            float dotA = __uint_as_float(lo) + __uint_as_float(hi);
            asm("mov.b64 {%0, %1}, %2;" : "=r"(lo), "=r"(hi) : "l"(sB));
            float dotB = __uint_as_float(lo) + __uint_as_float(hi);
            aA = __logf(dotA) + MA + eA;                   // t < lenA always here
            if (t < lenB) aB = __logf(dotB) + MB + eB;
            MA = MrA; MB = MrB;
            eA = nA; eB = nB;
            cur ^= 1;
        }

        // ---- logZ + sequence score per batch, deterministic reductions ----
        #pragma unroll 1
        for (int pass = 0; pass < 2; ++pass) {
            float a = pass ? aB : aA;
            int   b = pass ? bB : bA;
            int  ln = pass ? lenB : lenA;
            const float* lgb = pass ? lgB : lgA;
            unsigned wk = __reduce_max_sync(0xFFFFFFFFu, fkey(a));
            if (lane == 0) s_wkey[wid] = wk;
            __syncthreads();
            unsigned ak = max(max(s_wkey[0], s_wkey[1]), max(s_wkey[2], s_wkey[3]));
            float Mx = fval(ak);
            float e = __expf(a - Mx);
            #pragma unroll
            for (int m = 16; m > 0; m >>= 1) e += __shfl_xor_sync(0xFFFFFFFFu, e, m);
            if (lane == 0) s_red[wid] = e;

            const int* lab = labels + b * TT;
            float sc = 0.f;
            for (int t = tid; t < ln; t += 128) {
                int l = lab[t];
                sc += lgb[t * KK + l];
                if (t >= 1) sc += trans[lab[t - 1] * KK + l];
            }
            #pragma unroll
            for (int m = 16; m > 0; m >>= 1) sc += __shfl_xor_sync(0xFFFFFFFFu, sc, m);
            if (lane == 0) s_red[8 + wid] = sc;
            __syncthreads();
            if (tid == 0) {
                float S  = s_red[0] + s_red[1] + s_red[2] + s_red[3];
                float SC = s_red[8] + s_red[9] + s_red[10] + s_red[11];
                g_nll[b] = (__logf(S) + Mx) - SC;
            }
            __syncthreads();
        }
    }
}

// Deterministic final reduction: loss = sum_b nll[b]
extern "C" __global__ void crf_loss(float* __restrict__ out)
{
    __shared__ float s[BB];
    int tid = threadIdx.x;
    s[tid] = g_nll[tid];
    __syncthreads();
    for (int m = BB / 2; m > 0; m >>= 1) {
        if (tid < m) s[tid] += s[tid + m];
        __syncthreads();
    }
    if (tid == 0) out[0] = s[0];
}

extern "C" void kernel_launch(void* const* d_in, const int* in_sizes, int n_in,
                              void* d_out, int out_size)
{
    const float* logits   = (const float*)d_in[0];
    const int*   labels   = (const int*)d_in[1];
    const int*   seq_lens = (const int*)d_in[2];
    const float* trans    = (const float*)d_in[3];
    float* out = (float*)d_out;

    cudaFuncSetAttribute(crf_fwd, cudaFuncAttributeMaxDynamicSharedMemorySize, SMEM_BYTES);
    crf_fwd<<<384, 128, SMEM_BYTES>>>(logits, labels, seq_lens, trans, out);
    crf_loss<<<1, BB>>>(out);
}